// round 15
// baseline (speedup 1.0000x reference)
#include <cuda_runtime.h>
#include <cuda_bf16.h>

// SmoothnessLoss: loss = mean_i( (sHat_i - sY_i)^2 ), i in [0, W), W = N-k-1
// s_i = sum_{j<k} | x[i+j] - mean_j |, k = 64.
// Pair identity: |a-m|+|b-m| = max(|a-b|, |(a+b)-2m|).
// This round: warp-uniform parity (no divergence) + two-pass pair-major
// accumulation (no s/d arrays -> no register spills).

#define K_WIN 64
#define BLOCK 256
#define WPT 8
#define SPAN 16                               // window span per thread
#define STRIDE ((BLOCK / 2) * SPAN)           // 2048 windows per block-iter
#define GRID 296                              // 2 blocks/SM x 148 SMs

__device__ float g_partials[GRID];
__device__ unsigned int g_count = 0;

__device__ __forceinline__ float4 ldg4(const float4* p) {
    float4 v;
    asm volatile("ld.global.nc.v4.f32 {%0,%1,%2,%3}, [%4];"
                 : "=f"(v.x), "=f"(v.y), "=f"(v.z), "=f"(v.w) : "l"(p));
    return v;
}

// Accumulate pair p (values a,b) into the windows that contain it.
// Window j (j=0..7) covers pairs [j, j+31]. p is a compile-time constant at
// every call site (fully unrolled) so the guard prunes statically.
__device__ __forceinline__ void pair_acc(int p, float a, float b,
                                         const float twoM[WPT], float acc[WPT])
{
    const float s = a + b;
    const float ad = fabsf(a - b);
    #pragma unroll
    for (int j = 0; j < WPT; j++)
        if (j <= p && j + 31 >= p)
            acc[j] += fmaxf(ad, fabsf(s - twoM[j]));
}

// ---- Pass 1: window means. PAR selects pairing; low live state. ----
template <int PAR>
__device__ __forceinline__ void seg8_means(const float4* __restrict__ f4,
                                           float twoM[WPT])
{
    float sB0[7], sB1[7];                     // pair sums 0..6 and 32..38
    float A0 = 0.f, A1 = 0.f, A2 = 0.f, A3 = 0.f;

    if (PAR == 0) {
        // pair 2q = (c_q.x, c_q.y), pair 2q+1 = (c_q.z, c_q.w)
        #pragma unroll
        for (int g = 0; g < 4; g++) {         // chunks 4g..4g+3 -> pairs 8g..8g+7
            float4 c0 = ldg4(f4 + 4*g), c1 = ldg4(f4 + 4*g + 1);
            float4 c2 = ldg4(f4 + 4*g + 2), c3 = ldg4(f4 + 4*g + 3);
            float s0 = c0.x + c0.y, s1 = c0.z + c0.w;
            float s2 = c1.x + c1.y, s3 = c1.z + c1.w;
            float s4 = c2.x + c2.y, s5 = c2.z + c2.w;
            float s6 = c3.x + c3.y, s7 = c3.z + c3.w;
            A0 += s0; A1 += s1; A2 += s2; A3 += s3;
            A0 += s4; A1 += s5; A2 += s6; A3 += s7;
            if (g == 0) { sB0[0]=s0; sB0[1]=s1; sB0[2]=s2; sB0[3]=s3;
                          sB0[4]=s4; sB0[5]=s5; sB0[6]=s6; }
        }
        float4 c0 = ldg4(f4 + 16), c1 = ldg4(f4 + 17);
        float4 c2 = ldg4(f4 + 18), c3 = ldg4(f4 + 19);
        sB1[0] = c0.x + c0.y; sB1[1] = c0.z + c0.w;
        sB1[2] = c1.x + c1.y; sB1[3] = c1.z + c1.w;
        sB1[4] = c2.x + c2.y; sB1[5] = c2.z + c2.w;
        sB1[6] = c3.x + c3.y;
    } else {
        // pair 2q = (c_q.y, c_q.z), pair 2q+1 = (c_q.w, c_{q+1}.x)
        float4 cp = ldg4(f4);
        float s0 = cp.y + cp.z;
        A0 = s0; sB0[0] = s0;
        float pw = cp.w;
        #pragma unroll
        for (int g = 0; g < 4; g++) {         // chunks 4g+1..4g+4 -> pairs 8g+1..8g+8
            float4 c0 = ldg4(f4 + 4*g + 1), c1 = ldg4(f4 + 4*g + 2);
            float4 c2 = ldg4(f4 + 4*g + 3), c3 = ldg4(f4 + 4*g + 4);
            float t1 = pw  + c0.x, t2 = c0.y + c0.z;
            float t3 = c0.w + c1.x, t4 = c1.y + c1.z;
            float t5 = c1.w + c2.x, t6 = c2.y + c2.z;
            float t7 = c2.w + c3.x, t8 = c3.y + c3.z;
            A1 += t1; A2 += t2; A3 += t3; A0 += t4;
            A1 += t5; A2 += t6; A3 += t7;
            if (g < 3) A0 += t8;              // pair 8g+8 < 32 only for g<3
            pw = c3.w;
            if (g == 0) { sB0[1]=t1; sB0[2]=t2; sB0[3]=t3;
                          sB0[4]=t4; sB0[5]=t5; sB0[6]=t6; }
            if (g == 3) sB1[0] = t8;          // pair 32
        }
        // pairs 33..38; entering pw = c16.w
        float4 c0 = ldg4(f4 + 17), c1 = ldg4(f4 + 18), c2 = ldg4(f4 + 19);
        sB1[1] = pw  + c0.x; sB1[2] = c0.y + c0.z;
        sB1[3] = c0.w + c1.x; sB1[4] = c1.y + c1.z;
        sB1[5] = c1.w + c2.x; sB1[6] = c2.y + c2.z;
    }

    float sw = (A0 + A1) + (A2 + A3);         // window-0 pair-sum total
    #pragma unroll
    for (int j = 0; j < WPT; j++) {
        twoM[j] = sw * (1.0f / 32.0f);        // 2*mean (mean = sw/64)
        if (j < 7) sw += sB1[j] - sB0[j];
    }
}

// ---- Pass 2: pair-major accumulation (reload via L1, transient s/d). ----
template <int PAR>
__device__ __forceinline__ void seg8_acc(const float4* __restrict__ f4,
                                         const float twoM[WPT], float acc[WPT])
{
    if (PAR == 0) {
        #pragma unroll
        for (int q = 0; q < 20; q++) {
            float4 c = ldg4(f4 + q);
            pair_acc(2 * q, c.x, c.y, twoM, acc);
            if (2 * q + 1 <= 38) pair_acc(2 * q + 1, c.z, c.w, twoM, acc);
        }
    } else {
        float4 cp = ldg4(f4);
        pair_acc(0, cp.y, cp.z, twoM, acc);
        float pw = cp.w;
        #pragma unroll
        for (int q = 1; q < 20; q++) {
            float4 c = ldg4(f4 + q);
            pair_acc(2 * q - 1, pw, c.x, twoM, acc);
            pair_acc(2 * q,     c.y, c.z, twoM, acc);
            pw = c.w;
        }
    }
}

template <int PAR>
__device__ __forceinline__ void seg8_both(const float* __restrict__ yh,
                                          const float* __restrict__ yy,
                                          int eb, float accH[WPT], float accY[WPT])
{
    const float4* h4 = reinterpret_cast<const float4*>(yh + eb);
    const float4* y4 = reinterpret_cast<const float4*>(yy + eb);
    float twoMH[WPT], twoMY[WPT];
    seg8_means<PAR>(h4, twoMH);
    seg8_means<PAR>(y4, twoMY);
    seg8_acc<PAR>(h4, twoMH, accH);
    seg8_acc<PAR>(y4, twoMY, accY);
}

// Tail fallback: one window, elements p[0..63] (in-bounds for all w < W).
__device__ float window_scalar(const float* __restrict__ p)
{
    float s0 = 0.f, s1 = 0.f, s2 = 0.f, s3 = 0.f;
    #pragma unroll 1
    for (int i = 0; i < K_WIN; i += 4) {
        s0 += p[i]; s1 += p[i+1]; s2 += p[i+2]; s3 += p[i+3];
    }
    const float m = ((s0 + s1) + (s2 + s3)) * (1.0f / (float)K_WIN);
    float t0 = 0.f, t1 = 0.f;
    #pragma unroll 1
    for (int i = 0; i < K_WIN; i += 2) {
        t0 += fabsf(p[i]   - m);
        t1 += fabsf(p[i+1] - m);
    }
    return t0 + t1;
}

__global__ void __launch_bounds__(BLOCK, 2)
smoothness_persist_kernel(const float* __restrict__ yh,
                          const float* __restrict__ yy,
                          int W, int N, int WB,
                          float* __restrict__ out, double invW)
{
    __shared__ float  redf[BLOCK / 32];
    __shared__ double redd[BLOCK / 32];
    __shared__ int    amLast;

    const int tid  = threadIdx.x;
    const int wid  = tid >> 5;
    const int par  = wid & 1;                      // warp-uniform parity
    const int upos = ((tid >> 6) << 5) | (tid & 31);   // 0..127
    const int wstart = blockIdx.x * WB;            // multiple of 16
    const int wend   = min(wstart + WB, W);

    float d2 = 0.0f;

    #pragma unroll 1
    for (int g0 = wstart; g0 < wend; g0 += STRIDE) {
        const int eb = g0 + SPAN * upos;           // float4-aligned element base
        const int w0 = eb + par;                   // first window of this thread
        if (w0 >= wend) continue;

        float aH[WPT], aY[WPT];
        #pragma unroll
        for (int j = 0; j < WPT; j++) { aH[j] = 0.f; aY[j] = 0.f; }

        if (eb + 80 <= N) {
            if (par == 0) seg8_both<0>(yh, yy, eb, aH, aY);
            else          seg8_both<1>(yh, yy, eb, aH, aY);
        } else {
            #pragma unroll 1
            for (int j = 0; j < WPT; j++) {
                const int w = w0 + 2 * j;
                if (w < wend) {
                    aH[j] = window_scalar(yh + w);
                    aY[j] = window_scalar(yy + w);
                }
            }
        }

        #pragma unroll
        for (int j = 0; j < WPT; j++) {
            if (w0 + 2 * j < wend) {
                const float dd = aH[j] - aY[j];
                d2 += dd * dd;
            }
        }
    }

    // Block reduction of d2.
    #pragma unroll
    for (int off = 16; off > 0; off >>= 1)
        d2 += __shfl_down_sync(0xffffffffu, d2, off);

    const int lane = tid & 31;
    if (lane == 0) redf[wid] = d2;
    __syncthreads();
    if (wid == 0) {
        float vv = (lane < BLOCK / 32) ? redf[lane] : 0.0f;
        #pragma unroll
        for (int off = 4; off > 0; off >>= 1)
            vv += __shfl_down_sync(0xffffffffu, vv, off);
        if (lane == 0) {
            g_partials[blockIdx.x] = vv;
            __threadfence();
            unsigned int c = atomicAdd(&g_count, 1u);
            amLast = (c == (unsigned int)(gridDim.x - 1));
        }
    }
    __syncthreads();

    if (amLast) {
        // Deterministic final reduction (fixed order/topology).
        double sd = 0.0;
        #pragma unroll 1
        for (int i = tid; i < GRID; i += BLOCK)
            sd += (double)g_partials[i];
        #pragma unroll
        for (int off = 16; off > 0; off >>= 1)
            sd += __shfl_down_sync(0xffffffffu, sd, off);
        if (lane == 0) redd[wid] = sd;
        __syncthreads();
        if (wid == 0) {
            double vv = (lane < BLOCK / 32) ? redd[lane] : 0.0;
            #pragma unroll
            for (int off = 4; off > 0; off >>= 1)
                vv += __shfl_down_sync(0xffffffffu, vv, off);
            if (lane == 0) {
                out[0] = (float)(vv * invW);
                g_count = 0;                 // reset for next graph replay
            }
        }
    }
}

extern "C" void kernel_launch(void* const* d_in, const int* in_sizes, int n_in,
                              void* d_out, int out_size)
{
    const float* yh = (const float*)d_in[0];
    const float* yy = (const float*)d_in[1];
    const int N = in_sizes[0];
    const int W = N - K_WIN - 1;
    int WB = (W + GRID - 1) / GRID;
    WB = (WB + 15) & ~15;                        // multiple of 16 (SPAN/alignment)

    smoothness_persist_kernel<<<GRID, BLOCK>>>(yh, yy, W, N, WB,
                                               (float*)d_out, 1.0 / (double)W);
}